// round 2
// baseline (speedup 1.0000x reference)
#include <cuda_runtime.h>
#include <cuda_bf16.h>
#include <cstdint>

// Problem constants
#define B_   1024
#define T_   128
#define OBS_ 256
#define LAT_ 64
#define HID_ 512
#define ENC_ 512
#define GP_  128
#define BT_  (B_ * T_)   // 131072

// ---------------------------------------------------------------------------
// Static device scratch (allocation-free rule)
// ---------------------------------------------------------------------------
__device__ float g_buf0[(size_t)BT_ * 512];   // enc stage ping / rec stage ping (256MB)
__device__ float g_buf1[(size_t)BT_ * 512];   // enc_contrib (live through seq pass) / rec pong
__device__ float g_z[(size_t)BT_ * LAT_];     // z for deferred decoder
__device__ float g_tmp[(size_t)B_ * 2560];    // S1 out: pri_a0(512) | pos_a0(512) | gh(1536)
__device__ float g_a1[(size_t)B_ * 1024];     // S2 out: pri_a1(512) | pos_a1(512)
__device__ float g_out2[(size_t)B_ * 256];    // S3 out: pri2(128) | pos2(128)
__device__ float g_h[(size_t)B_ * HID_];      // recurrent state
__device__ float g_wiht[64 * 1536];           // Wih transposed [K=64][1536]

// ---------------------------------------------------------------------------
// Grouped GEMM:  C[:, n_off[g]:n_off[g+1]] = act( A_g @ W_g^T + bias_g + add_g )
// A_g: [M,K] row-major (ld lda), W_g: [n_sub,K] row-major (ld ldw)
// ---------------------------------------------------------------------------
#define MAX_G 4
struct GemmDesc {
    const float* A[MAX_G];    int lda[MAX_G];
    const float* W[MAX_G];    int ldw[MAX_G];
    const float* bias[MAX_G];
    const float* add[MAX_G];  long ldadd[MAX_G];
    int  n_off[MAX_G + 1];
    int  act[MAX_G];          // 1 = ELU
    float* C; int ldc;
    int M, K, Ntot, ng;
};

__device__ __forceinline__ float eluf(float x) { return x > 0.f ? x : expm1f(x); }

template <int BM, int BN, int BK, int TM, int TN>
__global__ void gemm_grouped(GemmDesc d) {
    constexpr int THREADS = (BM / TM) * (BN / TN);
    __shared__ float As[BK][BM + 4];
    __shared__ float Ws[BK][BN + 4];

    const int n0 = blockIdx.x * BN;
    const int m0 = blockIdx.y * BM;

    int g = 0;
    while (g + 1 < d.ng && n0 >= d.n_off[g + 1]) g++;

    const float* A  = d.A[g];   const int lda = d.lda[g];
    const float* W  = d.W[g];   const int ldw = d.ldw[g];
    const int nl0 = n0 - d.n_off[g];

    const int tid = threadIdx.x;
    const int tx = tid % (BN / TN);
    const int ty = tid / (BN / TN);

    float acc[TM][TN];
#pragma unroll
    for (int i = 0; i < TM; i++)
#pragma unroll
        for (int j = 0; j < TN; j++) acc[i][j] = 0.f;

    const int AV = BM * BK / 4;
    const int WV = BN * BK / 4;

    for (int k0 = 0; k0 < d.K; k0 += BK) {
#pragma unroll 2
        for (int v = tid; v < AV; v += THREADS) {
            int row = v / (BK / 4), c4 = v % (BK / 4);
            float4 q = *reinterpret_cast<const float4*>(A + (size_t)(m0 + row) * lda + k0 + c4 * 4);
            int kk = c4 * 4;
            As[kk + 0][row] = q.x; As[kk + 1][row] = q.y;
            As[kk + 2][row] = q.z; As[kk + 3][row] = q.w;
        }
#pragma unroll 2
        for (int v = tid; v < WV; v += THREADS) {
            int row = v / (BK / 4), c4 = v % (BK / 4);
            float4 q = *reinterpret_cast<const float4*>(W + (size_t)(nl0 + row) * ldw + k0 + c4 * 4);
            int kk = c4 * 4;
            Ws[kk + 0][row] = q.x; Ws[kk + 1][row] = q.y;
            Ws[kk + 2][row] = q.z; Ws[kk + 3][row] = q.w;
        }
        __syncthreads();

#pragma unroll
        for (int kk = 0; kk < BK; kk++) {
            float a[TM], b[TN];
#pragma unroll
            for (int i = 0; i < TM; i++) a[i] = As[kk][ty * TM + i];
#pragma unroll
            for (int j = 0; j < TN; j++) b[j] = Ws[kk][tx * TN + j];
#pragma unroll
            for (int i = 0; i < TM; i++)
#pragma unroll
                for (int j = 0; j < TN; j++) acc[i][j] = fmaf(a[i], b[j], acc[i][j]);
        }
        __syncthreads();
    }

    const float* bias = d.bias[g];
    const float* add  = d.add[g];
    const long   ldadd = d.ldadd[g];
    const int    act  = d.act[g];

#pragma unroll
    for (int i = 0; i < TM; i++) {
        const int m = m0 + ty * TM + i;
#pragma unroll
        for (int j = 0; j < TN; j++) {
            const int n  = n0 + tx * TN + j;
            const int nl = nl0 + tx * TN + j;
            float v = acc[i][j];
            if (bias) v += bias[nl];
            if (add)  v += add[(size_t)m * ldadd + nl];
            if (act)  v = eluf(v);
            d.C[(size_t)m * d.ldc + n] = v;
        }
    }
}

// ---------------------------------------------------------------------------
// Pack Wih^T (and nothing else)
// ---------------------------------------------------------------------------
__global__ void pack_wiht(const float* __restrict__ Wih) {
    int idx = blockIdx.x * blockDim.x + threadIdx.x;
    if (idx < 1536 * 64) {
        int row = idx / 64, k = idx % 64;
        g_wiht[k * 1536 + row] = Wih[idx];
    }
}

// ---------------------------------------------------------------------------
// Fused latent + GRU kernel (per timestep).
// Reads g_out2 (pri2|pos2), g_tmp (gh part), eps; writes z (smem + g_z),
// kl, mu, and updates g_h in place. gi = z @ Wih^T computed via g_wiht.
// ---------------------------------------------------------------------------
#define TMB 4
__global__ void gru_latent_kernel(const float* __restrict__ eps,
                                  const float* __restrict__ bih,
                                  float* __restrict__ kls_out,
                                  float* __restrict__ mu_out,
                                  int t) {
    __shared__ float zs[TMB][64];
    __shared__ float klw[TMB * 2];

    const int m0 = blockIdx.x * TMB;
    const int tid = threadIdx.x;   // 512 threads

    if (tid < TMB * 64) {
        const int r = tid >> 6, k = tid & 63;
        const int m = m0 + r;
        const float* o = g_out2 + (size_t)m * 256;
        float mu_p = o[k], ls_p = o[64 + k], mu_q = o[128 + k], ls_q = o[192 + k];
        float e = eps[((size_t)m * T_ + t) * 64 + k];
        float zl = fmaf(expf(ls_q), e, mu_q);
        zs[r][k] = zl;
        g_z[((size_t)m * T_ + t) * 64 + k]   = zl;
        mu_out[((size_t)m * T_ + t) * 64 + k] = mu_q;
        float dm = mu_q - mu_p;
        float klv = ls_p - ls_q + (expf(2.f * ls_q) + dm * dm) / (2.f * expf(2.f * ls_p)) - 0.5f;
#pragma unroll
        for (int off = 16; off > 0; off >>= 1)
            klv += __shfl_down_sync(0xffffffffu, klv, off);
        if ((tid & 31) == 0) klw[tid >> 5] = klv;
    }
    __syncthreads();
    if (tid < TMB) kls_out[(size_t)(m0 + tid) * T_ + t] = klw[2 * tid] + klw[2 * tid + 1];

    const int j = tid;  // 0..511
    float ar[TMB], az[TMB], an[TMB];
#pragma unroll
    for (int r = 0; r < TMB; r++) { ar[r] = 0.f; az[r] = 0.f; an[r] = 0.f; }

#pragma unroll 8
    for (int k = 0; k < 64; k++) {
        float wr = g_wiht[k * 1536 + j];
        float wz = g_wiht[k * 1536 + 512 + j];
        float wn = g_wiht[k * 1536 + 1024 + j];
#pragma unroll
        for (int r = 0; r < TMB; r++) {
            float zk = zs[r][k];
            ar[r] = fmaf(zk, wr, ar[r]);
            az[r] = fmaf(zk, wz, az[r]);
            an[r] = fmaf(zk, wn, an[r]);
        }
    }

    const float br = bih[j], bz = bih[512 + j], bn = bih[1024 + j];
#pragma unroll
    for (int r = 0; r < TMB; r++) {
        const int m = m0 + r;
        const float* tr = g_tmp + (size_t)m * 2560;
        float ghr = tr[1024 + j], ghz = tr[1536 + j], ghn = tr[2048 + j];
        float rg = 1.f / (1.f + expf(-(ar[r] + br + ghr)));
        float zg = 1.f / (1.f + expf(-(az[r] + bz + ghz)));
        float ng = tanhf(an[r] + bn + rg * ghn);
        float hv = g_h[(size_t)m * 512 + j];
        g_h[(size_t)m * 512 + j] = (1.f - zg) * ng + zg * hv;
    }
}

// ---------------------------------------------------------------------------
// Host launch helpers
// ---------------------------------------------------------------------------
static inline GemmDesc make_desc(float* C, int ldc, int M, int K) {
    GemmDesc d{};
    d.C = C; d.ldc = ldc; d.M = M; d.K = K; d.Ntot = 0; d.ng = 0;
    return d;
}
static inline void add_group(GemmDesc& d, int nsub,
                             const float* A, int lda,
                             const float* W, int ldw,
                             const float* bias, int act,
                             const float* add = nullptr, long ldadd = 0) {
    int g = d.ng;
    d.A[g] = A; d.lda[g] = lda;
    d.W[g] = W; d.ldw[g] = ldw;
    d.bias[g] = bias; d.act[g] = act;
    d.add[g] = add; d.ldadd[g] = ldadd;
    d.n_off[g] = d.Ntot;
    d.Ntot += nsub;
    d.n_off[g + 1] = d.Ntot;
    d.ng = g + 1;
}

template <int BM, int BN, int BK, int TM, int TN>
static inline void launch_gemm(const GemmDesc& d) {
    dim3 grid(d.Ntot / BN, d.M / BM);
    dim3 block((BM / TM) * (BN / TN));
    gemm_grouped<BM, BN, BK, TM, TN><<<grid, block>>>(d);
}

extern "C" void kernel_launch(void* const* d_in, const int* in_sizes, int n_in,
                              void* d_out, int out_size) {
    const float* obs     = (const float*)d_in[0];
    const float* eps     = (const float*)d_in[1];
    const float* enc_W0  = (const float*)d_in[2];
    const float* enc_b0  = (const float*)d_in[3];
    const float* enc_W1  = (const float*)d_in[4];
    const float* enc_b1  = (const float*)d_in[5];
    const float* enc_W2  = (const float*)d_in[6];
    const float* enc_b2  = (const float*)d_in[7];
    const float* pri_W0  = (const float*)d_in[8];
    const float* pri_b0  = (const float*)d_in[9];
    const float* pri_W1  = (const float*)d_in[10];
    const float* pri_b1  = (const float*)d_in[11];
    const float* pri_W2  = (const float*)d_in[12];
    const float* pri_b2  = (const float*)d_in[13];
    const float* pos_W0  = (const float*)d_in[14];
    const float* pos_b0  = (const float*)d_in[15];
    const float* pos_W1  = (const float*)d_in[16];
    const float* pos_b1  = (const float*)d_in[17];
    const float* pos_W2  = (const float*)d_in[18];
    const float* pos_b2  = (const float*)d_in[19];
    const float* dec_W0  = (const float*)d_in[20];
    const float* dec_b0  = (const float*)d_in[21];
    const float* dec_W1  = (const float*)d_in[22];
    const float* dec_b1  = (const float*)d_in[23];
    const float* dec_W2  = (const float*)d_in[24];
    const float* dec_b2  = (const float*)d_in[25];
    const float* gru_Wih = (const float*)d_in[26];
    const float* gru_bih = (const float*)d_in[27];
    const float* gru_Whh = (const float*)d_in[28];
    const float* gru_bhh = (const float*)d_in[29];
    (void)in_sizes; (void)n_in; (void)out_size;

    float *buf0, *buf1, *zbuf, *tmp, *a1, *out2, *h;
    cudaGetSymbolAddress((void**)&buf0, g_buf0);
    cudaGetSymbolAddress((void**)&buf1, g_buf1);
    cudaGetSymbolAddress((void**)&zbuf, g_z);
    cudaGetSymbolAddress((void**)&tmp,  g_tmp);
    cudaGetSymbolAddress((void**)&a1,   g_a1);
    cudaGetSymbolAddress((void**)&out2, g_out2);
    cudaGetSymbolAddress((void**)&h,    g_h);

    float* recons = (float*)d_out;                        // [B,T,OBS]
    float* kls    = recons + (size_t)BT_ * OBS_;          // [B,T]
    float* mu     = kls + BT_;                            // [B,T,LAT]

    // init
    cudaMemsetAsync(h, 0, (size_t)B_ * HID_ * sizeof(float));
    pack_wiht<<<(1536 * 64 + 255) / 256, 256>>>(gru_Wih);

    // ---- Parallel precompute: encoder over all (B*T) rows ----
    {
        GemmDesc d = make_desc(buf0, 512, BT_, 256);                 // enc L0
        add_group(d, 512, obs, 256, enc_W0, 256, enc_b0, 1);
        launch_gemm<128, 128, 16, 8, 8>(d);
    }
    {
        GemmDesc d = make_desc(buf1, 512, BT_, 512);                 // enc L1
        add_group(d, 512, buf0, 512, enc_W1, 512, enc_b1, 1);
        launch_gemm<128, 128, 16, 8, 8>(d);
    }
    {
        GemmDesc d = make_desc(buf0, 512, BT_, 512);                 // enc L2 (no act)
        add_group(d, 512, buf1, 512, enc_W2, 512, enc_b2, 0);
        launch_gemm<128, 128, 16, 8, 8>(d);
    }
    {
        // enc contribution to pos L0 (+ pos_b0 folded in): buf1 = enc @ pos_W0[:,512:]^T + pos_b0
        GemmDesc d = make_desc(buf1, 512, BT_, 512);
        add_group(d, 512, buf0, 512, pos_W0 + 512, 1024, pos_b0, 0);
        launch_gemm<128, 128, 16, 8, 8>(d);
    }

    // ---- Sequential recurrence ----
    for (int t = 0; t < T_; t++) {
        // S1: h -> [pri_a0 | pos_a0 | gh]   (N = 2560, K = 512)
        {
            GemmDesc d = make_desc(tmp, 2560, B_, 512);
            add_group(d, 512,  h, 512, pri_W0,  512, pri_b0,  1);
            add_group(d, 512,  h, 512, pos_W0, 1024, nullptr, 1,
                      buf1 + (size_t)t * 512, (long)T_ * 512);
            add_group(d, 1536, h, 512, gru_Whh, 512, gru_bhh, 0);
            launch_gemm<64, 128, 16, 8, 8>(d);
        }
        // S2: [pri_a1 | pos_a1]   (N = 1024, K = 512)
        {
            GemmDesc d = make_desc(a1, 1024, B_, 512);
            add_group(d, 512, tmp,       2560, pri_W1, 512, pri_b1, 1);
            add_group(d, 512, tmp + 512, 2560, pos_W1, 512, pos_b1, 1);
            launch_gemm<64, 128, 16, 8, 8>(d);
        }
        // S3: [pri2 | pos2]   (N = 256, K = 512)
        {
            GemmDesc d = make_desc(out2, 256, B_, 512);
            add_group(d, 128, a1,       1024, pri_W2, 512, pri_b2, 0);
            add_group(d, 128, a1 + 512, 1024, pos_W2, 512, pos_b2, 0);
            launch_gemm<64, 128, 16, 8, 8>(d);
        }
        // S4: latent sample + kl + mu + GRU update
        gru_latent_kernel<<<B_ / TMB, 512>>>(eps, gru_bih, kls, mu, t);
    }

    // ---- Deferred decoder over all (B*T) rows ----
    {
        GemmDesc d = make_desc(buf0, 512, BT_, 64);                  // dec L0
        add_group(d, 512, zbuf, 64, dec_W0, 64, dec_b0, 1);
        launch_gemm<128, 128, 16, 8, 8>(d);
    }
    {
        GemmDesc d = make_desc(buf1, 512, BT_, 512);                 // dec L1
        add_group(d, 512, buf0, 512, dec_W1, 512, dec_b1, 1);
        launch_gemm<128, 128, 16, 8, 8>(d);
    }
    {
        GemmDesc d = make_desc(recons, 256, BT_, 512);               // dec L2 -> output
        add_group(d, 256, buf1, 512, dec_W2, 512, dec_b2, 0);
        launch_gemm<128, 128, 16, 8, 8>(d);
    }
}

// round 4
// speedup vs baseline: 2.0172x; 2.0172x over previous
#include <cuda_runtime.h>
#include <cuda_bf16.h>
#include <cstdint>

// Problem constants
#define B_   1024
#define T_   128
#define OBS_ 256
#define LAT_ 64
#define HID_ 512
#define BT_  (B_ * T_)   // 131072

// ---------------------------------------------------------------------------
// Static device scratch (allocation-free rule)
// ---------------------------------------------------------------------------
__device__ float g_buf0[(size_t)BT_ * 512];
__device__ float g_buf1[(size_t)BT_ * 512];
__device__ float g_z[(size_t)BT_ * LAT_];
__device__ float g_tmp[(size_t)B_ * 2560];    // pri_a0(512) | pos_a0(512) | gh(1536)
__device__ float g_a1[(size_t)B_ * 1024];
__device__ float g_out2[(size_t)B_ * 256];
__device__ float g_h[(size_t)B_ * HID_];
__device__ float g_wiht[64 * 1536];

// Packed bf16 hi/lo weights (filled once per launch)
enum : int {
    OFF_encW0  = 0,
    OFF_encW1  = OFF_encW0  + 512 * 256,
    OFF_encW2  = OFF_encW1  + 512 * 512,
    OFF_posW0e = OFF_encW2  + 512 * 512,
    OFF_posW0h = OFF_posW0e + 512 * 512,
    OFF_priW0  = OFF_posW0h + 512 * 512,
    OFF_gruWhh = OFF_priW0  + 512 * 512,
    OFF_priW1  = OFF_gruWhh + 1536 * 512,
    OFF_posW1  = OFF_priW1  + 512 * 512,
    OFF_priW2  = OFF_posW1  + 512 * 512,
    OFF_posW2  = OFF_priW2  + 128 * 512,
    OFF_decW0  = OFF_posW2  + 128 * 512,
    OFF_decW1  = OFF_decW0  + 512 * 64,
    OFF_decW2  = OFF_decW1  + 512 * 512,
    WTOT       = OFF_decW2  + 256 * 512
};
__device__ __nv_bfloat16 g_whi[WTOT];
__device__ __nv_bfloat16 g_wlo[WTOT];

__device__ __forceinline__ float eluf(float x) { return x > 0.f ? x : expm1f(x); }

// ---------------------------------------------------------------------------
// mma.sync bf16 (sm_80+ PTX — compiles at plain compute_103, lowers to HMMA)
// ---------------------------------------------------------------------------
__device__ __forceinline__ void mma_bf16(float* c, const uint32_t* a, uint32_t b0, uint32_t b1) {
    asm volatile(
        "mma.sync.aligned.m16n8k16.row.col.f32.bf16.bf16.f32 "
        "{%0,%1,%2,%3}, {%4,%5,%6,%7}, {%8,%9}, {%0,%1,%2,%3};"
        : "+f"(c[0]), "+f"(c[1]), "+f"(c[2]), "+f"(c[3])
        : "r"(a[0]), "r"(a[1]), "r"(a[2]), "r"(a[3]), "r"(b0), "r"(b1));
}

// ---------------------------------------------------------------------------
// Grouped tensor-core GEMM: C[:, n_off[g]:] = act( A_g @ W_g^T + bias + add )
// A: fp32 [M,K] (lda). W: packed bf16 hi/lo, K-major, ld = K.
// Tile 128x128, BK=32, bf16 hi/lo 3-MMA emulation, fp32 accum.
// 256 threads = 8 warps: warp_m = wid&1 (64 rows), warp_n = wid>>1 (32 cols).
// ---------------------------------------------------------------------------
struct GemmTC {
    const float* A[4];    int lda[4];
    const __nv_bfloat16* Whi[4];
    const __nv_bfloat16* Wlo[4];
    const float* bias[4];
    const float* add[4];  long ldadd[4];
    int n_off[5];
    int act[4];
    float* C; int ldc;
    int M, K, Ntot, ng;
};

#define SROW 40   // padded row length (bf16) -> 80B = 20 words; conflict-free frag loads

__global__ void __launch_bounds__(256) gemm_tc(GemmTC d) {
    __shared__ __align__(16) __nv_bfloat16 sAh[128 * SROW];
    __shared__ __align__(16) __nv_bfloat16 sAl[128 * SROW];
    __shared__ __align__(16) __nv_bfloat16 sWh[128 * SROW];
    __shared__ __align__(16) __nv_bfloat16 sWl[128 * SROW];

    const int tid = threadIdx.x;
    const int wid = tid >> 5;
    const int lane = tid & 31;
    const int gid = lane >> 2;      // group id (row within frag)
    const int tig = lane & 3;       // thread-in-group (k/n pair select)

    const int n0 = blockIdx.x * 128;
    const int m0 = blockIdx.y * 128;
    int g = 0;
    while (g + 1 < d.ng && n0 >= d.n_off[g + 1]) g++;
    const float* A = d.A[g];
    const int lda = d.lda[g];
    const __nv_bfloat16* Whi = d.Whi[g];
    const __nv_bfloat16* Wlo = d.Wlo[g];
    const int nl0 = n0 - d.n_off[g];
    const int Kd = d.K;
    const int NC = Kd >> 5;

    const int warp_m = wid & 1;     // 0/1 -> 64-row halves
    const int warp_n = wid >> 1;    // 0..3 -> 32-col quarters

    float acc[4][4][4];
#pragma unroll
    for (int i = 0; i < 4; i++)
#pragma unroll
        for (int j = 0; j < 4; j++)
#pragma unroll
            for (int q = 0; q < 4; q++) acc[i][j][q] = 0.f;

    // per-thread gmem prefetch registers
    float av[16];
    uint4 wh[2], wl[2];

    // gmem load of chunk kc
    auto load_g = [&](int kc) {
        const int k0 = kc << 5;
#pragma unroll
        for (int i = 0; i < 4; i++) {
            const int idx = tid + i * 256;
            const int row = idx >> 3;
            const int col = (idx & 7) * 4;
            const float4 v = *reinterpret_cast<const float4*>(
                A + (size_t)(m0 + row) * lda + k0 + col);
            av[i * 4 + 0] = v.x; av[i * 4 + 1] = v.y;
            av[i * 4 + 2] = v.z; av[i * 4 + 3] = v.w;
        }
#pragma unroll
        for (int i = 0; i < 2; i++) {
            const int idx = tid + i * 256;
            const int row = idx >> 2;
            const int col = (idx & 3) * 8;
            const size_t go = (size_t)(nl0 + row) * Kd + k0 + col;
            wh[i] = *reinterpret_cast<const uint4*>(Whi + go);
            wl[i] = *reinterpret_cast<const uint4*>(Wlo + go);
        }
    };

    // stage prefetch registers into smem (fp32 -> bf16 hi/lo for A)
    auto stage = [&]() {
#pragma unroll
        for (int i = 0; i < 4; i++) {
            const int idx = tid + i * 256;
            const int row = idx >> 3;
            const int col = (idx & 7) * 4;
            float x0 = av[i * 4 + 0], x1 = av[i * 4 + 1];
            float x2 = av[i * 4 + 2], x3 = av[i * 4 + 3];
            __nv_bfloat162 h01 = __floats2bfloat162_rn(x0, x1);
            __nv_bfloat162 h23 = __floats2bfloat162_rn(x2, x3);
            __nv_bfloat162 l01 = __floats2bfloat162_rn(x0 - __bfloat162float(h01.x),
                                                       x1 - __bfloat162float(h01.y));
            __nv_bfloat162 l23 = __floats2bfloat162_rn(x2 - __bfloat162float(h23.x),
                                                       x3 - __bfloat162float(h23.y));
            const int so = row * SROW + col;
            *reinterpret_cast<uint32_t*>(&sAh[so])     = *reinterpret_cast<uint32_t*>(&h01);
            *reinterpret_cast<uint32_t*>(&sAh[so + 2]) = *reinterpret_cast<uint32_t*>(&h23);
            *reinterpret_cast<uint32_t*>(&sAl[so])     = *reinterpret_cast<uint32_t*>(&l01);
            *reinterpret_cast<uint32_t*>(&sAl[so + 2]) = *reinterpret_cast<uint32_t*>(&l23);
        }
#pragma unroll
        for (int i = 0; i < 2; i++) {
            const int idx = tid + i * 256;
            const int row = idx >> 2;
            const int col = (idx & 3) * 8;
            *reinterpret_cast<uint4*>(&sWh[row * SROW + col]) = wh[i];
            *reinterpret_cast<uint4*>(&sWl[row * SROW + col]) = wl[i];
        }
    };

    load_g(0);

    for (int kc = 0; kc < NC; kc++) {
        stage();
        __syncthreads();
        if (kc + 1 < NC) load_g(kc + 1);

#pragma unroll
        for (int ks = 0; ks < 32; ks += 16) {
            uint32_t ah[4][4], al[4][4];
            const int kk = ks + tig * 2;
#pragma unroll
            for (int mf = 0; mf < 4; mf++) {
                const int r0 = warp_m * 64 + mf * 16 + gid;
                ah[mf][0] = *reinterpret_cast<const uint32_t*>(&sAh[r0 * SROW + kk]);
                ah[mf][1] = *reinterpret_cast<const uint32_t*>(&sAh[(r0 + 8) * SROW + kk]);
                ah[mf][2] = *reinterpret_cast<const uint32_t*>(&sAh[r0 * SROW + kk + 8]);
                ah[mf][3] = *reinterpret_cast<const uint32_t*>(&sAh[(r0 + 8) * SROW + kk + 8]);
                al[mf][0] = *reinterpret_cast<const uint32_t*>(&sAl[r0 * SROW + kk]);
                al[mf][1] = *reinterpret_cast<const uint32_t*>(&sAl[(r0 + 8) * SROW + kk]);
                al[mf][2] = *reinterpret_cast<const uint32_t*>(&sAl[r0 * SROW + kk + 8]);
                al[mf][3] = *reinterpret_cast<const uint32_t*>(&sAl[(r0 + 8) * SROW + kk + 8]);
            }
#pragma unroll
            for (int nf = 0; nf < 4; nf++) {
                const int c0 = warp_n * 32 + nf * 8 + gid;
                const uint32_t bh0 = *reinterpret_cast<const uint32_t*>(&sWh[c0 * SROW + kk]);
                const uint32_t bh1 = *reinterpret_cast<const uint32_t*>(&sWh[c0 * SROW + kk + 8]);
                const uint32_t bl0 = *reinterpret_cast<const uint32_t*>(&sWl[c0 * SROW + kk]);
                const uint32_t bl1 = *reinterpret_cast<const uint32_t*>(&sWl[c0 * SROW + kk + 8]);
#pragma unroll
                for (int mf = 0; mf < 4; mf++) {
                    mma_bf16(acc[mf][nf], ah[mf], bh0, bh1);
                    mma_bf16(acc[mf][nf], ah[mf], bl0, bl1);
                    mma_bf16(acc[mf][nf], al[mf], bh0, bh1);
                }
            }
        }
        __syncthreads();
    }

    // Epilogue: bias + add + ELU, float2 stores
    const float* bias = d.bias[g];
    const float* add  = d.add[g];
    const long   ldadd = d.ldadd[g];
    const int    act  = d.act[g];

#pragma unroll
    for (int mf = 0; mf < 4; mf++) {
        const int r0 = m0 + warp_m * 64 + mf * 16 + gid;
#pragma unroll
        for (int nf = 0; nf < 4; nf++) {
            const int coll = warp_n * 32 + nf * 8 + tig * 2;  // local col in tile
            const int col  = n0 + coll;
            const int nlc  = nl0 + coll;
            float v0 = acc[mf][nf][0], v1 = acc[mf][nf][1];
            float v2 = acc[mf][nf][2], v3 = acc[mf][nf][3];
            if (bias) {
                const float b0v = bias[nlc], b1v = bias[nlc + 1];
                v0 += b0v; v1 += b1v; v2 += b0v; v3 += b1v;
            }
            if (add) {
                const float2 a0 = *reinterpret_cast<const float2*>(add + (size_t)r0 * ldadd + nlc);
                const float2 a1 = *reinterpret_cast<const float2*>(add + (size_t)(r0 + 8) * ldadd + nlc);
                v0 += a0.x; v1 += a0.y; v2 += a1.x; v3 += a1.y;
            }
            if (act) { v0 = eluf(v0); v1 = eluf(v1); v2 = eluf(v2); v3 = eluf(v3); }
            *reinterpret_cast<float2*>(d.C + (size_t)r0 * d.ldc + col)       = make_float2(v0, v1);
            *reinterpret_cast<float2*>(d.C + (size_t)(r0 + 8) * d.ldc + col) = make_float2(v2, v3);
        }
    }
}

// ---------------------------------------------------------------------------
// Weight packing: fp32 -> bf16 hi/lo
// ---------------------------------------------------------------------------
__global__ void pack_w(const float* __restrict__ src, int ld, int coff,
                       __nv_bfloat16* __restrict__ hi, __nv_bfloat16* __restrict__ lo,
                       int n, int K) {
    int i = blockIdx.x * 256 + threadIdx.x;
    if (i < n) {
        int r = i / K, k = i - r * K;
        float v = src[(size_t)r * ld + coff + k];
        __nv_bfloat16 h = __float2bfloat16(v);
        hi[i] = h;
        lo[i] = __float2bfloat16(v - __bfloat162float(h));
    }
}

__global__ void pack_wiht(const float* __restrict__ Wih) {
    int idx = blockIdx.x * blockDim.x + threadIdx.x;
    if (idx < 1536 * 64) {
        int row = idx / 64, k = idx % 64;
        g_wiht[k * 1536 + row] = Wih[idx];
    }
}

// ---------------------------------------------------------------------------
// Fused latent + GRU kernel (per timestep)
// ---------------------------------------------------------------------------
#define TMB 4
__global__ void gru_latent_kernel(const float* __restrict__ eps,
                                  const float* __restrict__ bih,
                                  float* __restrict__ kls_out,
                                  float* __restrict__ mu_out,
                                  int t) {
    __shared__ float zs[TMB][64];
    __shared__ float klw[TMB * 2];

    const int m0 = blockIdx.x * TMB;
    const int tid = threadIdx.x;

    if (tid < TMB * 64) {
        const int r = tid >> 6, k = tid & 63;
        const int m = m0 + r;
        const float* o = g_out2 + (size_t)m * 256;
        float mu_p = o[k], ls_p = o[64 + k], mu_q = o[128 + k], ls_q = o[192 + k];
        float e = eps[((size_t)m * T_ + t) * 64 + k];
        float zl = fmaf(expf(ls_q), e, mu_q);
        zs[r][k] = zl;
        g_z[((size_t)m * T_ + t) * 64 + k]    = zl;
        mu_out[((size_t)m * T_ + t) * 64 + k] = mu_q;
        float dm = mu_q - mu_p;
        float klv = ls_p - ls_q + (expf(2.f * ls_q) + dm * dm) / (2.f * expf(2.f * ls_p)) - 0.5f;
#pragma unroll
        for (int off = 16; off > 0; off >>= 1)
            klv += __shfl_down_sync(0xffffffffu, klv, off);
        if ((tid & 31) == 0) klw[tid >> 5] = klv;
    }
    __syncthreads();
    if (tid < TMB) kls_out[(size_t)(m0 + tid) * T_ + t] = klw[2 * tid] + klw[2 * tid + 1];

    const int j = tid;
    float ar[TMB], az[TMB], an[TMB];
#pragma unroll
    for (int r = 0; r < TMB; r++) { ar[r] = 0.f; az[r] = 0.f; an[r] = 0.f; }

#pragma unroll 8
    for (int k = 0; k < 64; k++) {
        float wr = g_wiht[k * 1536 + j];
        float wz = g_wiht[k * 1536 + 512 + j];
        float wn = g_wiht[k * 1536 + 1024 + j];
#pragma unroll
        for (int r = 0; r < TMB; r++) {
            float zk = zs[r][k];
            ar[r] = fmaf(zk, wr, ar[r]);
            az[r] = fmaf(zk, wz, az[r]);
            an[r] = fmaf(zk, wn, an[r]);
        }
    }

    const float br = bih[j], bz = bih[512 + j], bn = bih[1024 + j];
#pragma unroll
    for (int r = 0; r < TMB; r++) {
        const int m = m0 + r;
        const float* tr = g_tmp + (size_t)m * 2560;
        float ghr = tr[1024 + j], ghz = tr[1536 + j], ghn = tr[2048 + j];
        float rg = 1.f / (1.f + expf(-(ar[r] + br + ghr)));
        float zg = 1.f / (1.f + expf(-(az[r] + bz + ghz)));
        float ng = tanhf(an[r] + bn + rg * ghn);
        float hv = g_h[(size_t)m * 512 + j];
        g_h[(size_t)m * 512 + j] = (1.f - zg) * ng + zg * hv;
    }
}

// ---------------------------------------------------------------------------
// Host helpers
// ---------------------------------------------------------------------------
static inline GemmTC make_desc(float* C, int ldc, int M, int K) {
    GemmTC d{};
    d.C = C; d.ldc = ldc; d.M = M; d.K = K; d.Ntot = 0; d.ng = 0;
    return d;
}
static inline void add_group(GemmTC& d, int nsub,
                             const float* A, int lda,
                             const __nv_bfloat16* Whi, const __nv_bfloat16* Wlo,
                             const float* bias, int act,
                             const float* add = nullptr, long ldadd = 0) {
    int g = d.ng;
    d.A[g] = A; d.lda[g] = lda;
    d.Whi[g] = Whi; d.Wlo[g] = Wlo;
    d.bias[g] = bias; d.act[g] = act;
    d.add[g] = add; d.ldadd[g] = ldadd;
    d.n_off[g] = d.Ntot;
    d.Ntot += nsub;
    d.n_off[g + 1] = d.Ntot;
    d.ng = g + 1;
}
static inline void launch_tc(const GemmTC& d) {
    dim3 grid(d.Ntot / 128, d.M / 128);
    gemm_tc<<<grid, 256>>>(d);
}

extern "C" void kernel_launch(void* const* d_in, const int* in_sizes, int n_in,
                              void* d_out, int out_size) {
    const float* obs     = (const float*)d_in[0];
    const float* eps     = (const float*)d_in[1];
    const float* enc_W0  = (const float*)d_in[2];
    const float* enc_b0  = (const float*)d_in[3];
    const float* enc_W1  = (const float*)d_in[4];
    const float* enc_b1  = (const float*)d_in[5];
    const float* enc_W2  = (const float*)d_in[6];
    const float* enc_b2  = (const float*)d_in[7];
    const float* pri_W0  = (const float*)d_in[8];
    const float* pri_b0  = (const float*)d_in[9];
    const float* pri_W1  = (const float*)d_in[10];
    const float* pri_b1  = (const float*)d_in[11];
    const float* pri_W2  = (const float*)d_in[12];
    const float* pri_b2  = (const float*)d_in[13];
    const float* pos_W0  = (const float*)d_in[14];
    const float* pos_b0  = (const float*)d_in[15];
    const float* pos_W1  = (const float*)d_in[16];
    const float* pos_b1  = (const float*)d_in[17];
    const float* pos_W2  = (const float*)d_in[18];
    const float* pos_b2  = (const float*)d_in[19];
    const float* dec_W0  = (const float*)d_in[20];
    const float* dec_b0  = (const float*)d_in[21];
    const float* dec_W1  = (const float*)d_in[22];
    const float* dec_b1  = (const float*)d_in[23];
    const float* dec_W2  = (const float*)d_in[24];
    const float* dec_b2  = (const float*)d_in[25];
    const float* gru_Wih = (const float*)d_in[26];
    const float* gru_bih = (const float*)d_in[27];
    const float* gru_Whh = (const float*)d_in[28];
    const float* gru_bhh = (const float*)d_in[29];
    (void)in_sizes; (void)n_in; (void)out_size;

    float *buf0, *buf1, *zbuf, *tmp, *a1, *out2, *h;
    __nv_bfloat16 *whi, *wlo;
    cudaGetSymbolAddress((void**)&buf0, g_buf0);
    cudaGetSymbolAddress((void**)&buf1, g_buf1);
    cudaGetSymbolAddress((void**)&zbuf, g_z);
    cudaGetSymbolAddress((void**)&tmp,  g_tmp);
    cudaGetSymbolAddress((void**)&a1,   g_a1);
    cudaGetSymbolAddress((void**)&out2, g_out2);
    cudaGetSymbolAddress((void**)&h,    g_h);
    cudaGetSymbolAddress((void**)&whi,  g_whi);
    cudaGetSymbolAddress((void**)&wlo,  g_wlo);

    float* recons = (float*)d_out;
    float* kls    = recons + (size_t)BT_ * OBS_;
    float* mu     = kls + BT_;

    // init + weight packing
    cudaMemsetAsync(h, 0, (size_t)B_ * HID_ * sizeof(float));
    pack_wiht<<<(1536 * 64 + 255) / 256, 256>>>(gru_Wih);

    auto pk = [&](const float* src, int ld, int coff, int off, int rows, int K) {
        int n = rows * K;
        pack_w<<<(n + 255) / 256, 256>>>(src, ld, coff, whi + off, wlo + off, n, K);
    };
    pk(enc_W0, 256, 0,    OFF_encW0,  512, 256);
    pk(enc_W1, 512, 0,    OFF_encW1,  512, 512);
    pk(enc_W2, 512, 0,    OFF_encW2,  512, 512);
    pk(pos_W0, 1024, 512, OFF_posW0e, 512, 512);
    pk(pos_W0, 1024, 0,   OFF_posW0h, 512, 512);
    pk(pri_W0, 512, 0,    OFF_priW0,  512, 512);
    pk(gru_Whh, 512, 0,   OFF_gruWhh, 1536, 512);
    pk(pri_W1, 512, 0,    OFF_priW1,  512, 512);
    pk(pos_W1, 512, 0,    OFF_posW1,  512, 512);
    pk(pri_W2, 512, 0,    OFF_priW2,  128, 512);
    pk(pos_W2, 512, 0,    OFF_posW2,  128, 512);
    pk(dec_W0, 64, 0,     OFF_decW0,  512, 64);
    pk(dec_W1, 512, 0,    OFF_decW1,  512, 512);
    pk(dec_W2, 512, 0,    OFF_decW2,  256, 512);

    // ---- Parallel precompute: encoder over all (B*T) rows ----
    {
        GemmTC d = make_desc(buf0, 512, BT_, 256);
        add_group(d, 512, obs, 256, whi + OFF_encW0, wlo + OFF_encW0, enc_b0, 1);
        launch_tc(d);
    }
    {
        GemmTC d = make_desc(buf1, 512, BT_, 512);
        add_group(d, 512, buf0, 512, whi + OFF_encW1, wlo + OFF_encW1, enc_b1, 1);
        launch_tc(d);
    }
    {
        GemmTC d = make_desc(buf0, 512, BT_, 512);
        add_group(d, 512, buf1, 512, whi + OFF_encW2, wlo + OFF_encW2, enc_b2, 0);
        launch_tc(d);
    }
    {
        GemmTC d = make_desc(buf1, 512, BT_, 512);
        add_group(d, 512, buf0, 512, whi + OFF_posW0e, wlo + OFF_posW0e, pos_b0, 0);
        launch_tc(d);
    }

    // ---- Sequential recurrence ----
    for (int t = 0; t < T_; t++) {
        {
            GemmTC d = make_desc(tmp, 2560, B_, 512);
            add_group(d, 512,  h, 512, whi + OFF_priW0,  wlo + OFF_priW0,  pri_b0, 1);
            add_group(d, 512,  h, 512, whi + OFF_posW0h, wlo + OFF_posW0h, nullptr, 1,
                      buf1 + (size_t)t * 512, (long)T_ * 512);
            add_group(d, 1536, h, 512, whi + OFF_gruWhh, wlo + OFF_gruWhh, gru_bhh, 0);
            launch_tc(d);
        }
        {
            GemmTC d = make_desc(a1, 1024, B_, 512);
            add_group(d, 512, tmp,       2560, whi + OFF_priW1, wlo + OFF_priW1, pri_b1, 1);
            add_group(d, 512, tmp + 512, 2560, whi + OFF_posW1, wlo + OFF_posW1, pos_b1, 1);
            launch_tc(d);
        }
        {
            GemmTC d = make_desc(out2, 256, B_, 512);
            add_group(d, 128, a1,       1024, whi + OFF_priW2, wlo + OFF_priW2, pri_b2, 0);
            add_group(d, 128, a1 + 512, 1024, whi + OFF_posW2, wlo + OFF_posW2, pos_b2, 0);
            launch_tc(d);
        }
        gru_latent_kernel<<<B_ / TMB, 512>>>(eps, gru_bih, kls, mu, t);
    }

    // ---- Deferred decoder over all (B*T) rows ----
    {
        GemmTC d = make_desc(buf0, 512, BT_, 64);
        add_group(d, 512, zbuf, 64, whi + OFF_decW0, wlo + OFF_decW0, dec_b0, 1);
        launch_tc(d);
    }
    {
        GemmTC d = make_desc(buf1, 512, BT_, 512);
        add_group(d, 512, buf0, 512, whi + OFF_decW1, wlo + OFF_decW1, dec_b1, 1);
        launch_tc(d);
    }
    {
        GemmTC d = make_desc(recons, 256, BT_, 512);
        add_group(d, 256, buf1, 512, whi + OFF_decW2, wlo + OFF_decW2, dec_b2, 0);
        launch_tc(d);
    }
}